// round 7
// baseline (speedup 1.0000x reference)
#include <cuda_runtime.h>

#define D 128
#define D4 (D / 4)              // 32 float4 per row
#define THREADS 128
#define GROUPS (THREADS / 32)   // 4 row-groups
#define CHUNKS 8                // chunks per segment

#define MAX_CTAS 16384
#define MAX_B    4096
__device__ float g_part[MAX_CTAS][D];   // per-chunk partial sums
__device__ int   g_cnt[MAX_B];          // zero-initialized arrival counters

__global__ __launch_bounds__(THREADS, 8)
void seg_mean_kernel(const float* __restrict__ x,
                     const int* __restrict__ lens,
                     float* __restrict__ out)
{
    const int b   = blockIdx.x >> 3;          // segment (CHUNKS = 8)
    const int c   = blockIdx.x & (CHUNKS - 1);
    const int tid = threadIdx.x;

    // ---- segment start = sum(lens[0..b)) via block reduction ----
    __shared__ int sscan[THREADS];
    int partial = 0;
    for (int i = tid; i < b; i += THREADS) partial += __ldg(&lens[i]);
    sscan[tid] = partial;
    __syncthreads();
    #pragma unroll
    for (int s = THREADS / 2; s > 0; s >>= 1) {
        if (tid < s) sscan[tid] += sscan[tid + s];
        __syncthreads();
    }
    const int start = sscan[0];
    const int len   = __ldg(&lens[b]);

    const int r0 = (int)(((long long)c * len) / CHUNKS);
    const int r1 = (int)(((long long)(c + 1) * len) / CHUNKS);

    const float4* __restrict__ xv =
        reinterpret_cast<const float4*>(x) + (size_t)start * D4;
    const int cg = tid & 31;   // float4 column 0..31
    const int rg = tid >> 5;   // row group 0..3

    float4 a0 = make_float4(0.f, 0.f, 0.f, 0.f);
    float4 a1 = a0, a2 = a0, a3 = a0;

    int r = r0 + rg;
    // 8 independent in-flight LDG.128 per thread, 32 rows/iter
    for (; r + 7 * GROUPS < r1; r += 8 * GROUPS) {
        float4 v0 = xv[(size_t)(r + 0 * GROUPS) * D4 + cg];
        float4 v1 = xv[(size_t)(r + 1 * GROUPS) * D4 + cg];
        float4 v2 = xv[(size_t)(r + 2 * GROUPS) * D4 + cg];
        float4 v3 = xv[(size_t)(r + 3 * GROUPS) * D4 + cg];
        float4 v4 = xv[(size_t)(r + 4 * GROUPS) * D4 + cg];
        float4 v5 = xv[(size_t)(r + 5 * GROUPS) * D4 + cg];
        float4 v6 = xv[(size_t)(r + 6 * GROUPS) * D4 + cg];
        float4 v7 = xv[(size_t)(r + 7 * GROUPS) * D4 + cg];
        a0.x += v0.x; a0.y += v0.y; a0.z += v0.z; a0.w += v0.w;
        a1.x += v1.x; a1.y += v1.y; a1.z += v1.z; a1.w += v1.w;
        a2.x += v2.x; a2.y += v2.y; a2.z += v2.z; a2.w += v2.w;
        a3.x += v3.x; a3.y += v3.y; a3.z += v3.z; a3.w += v3.w;
        a0.x += v4.x; a0.y += v4.y; a0.z += v4.z; a0.w += v4.w;
        a1.x += v5.x; a1.y += v5.y; a1.z += v5.z; a1.w += v5.w;
        a2.x += v6.x; a2.y += v6.y; a2.z += v6.z; a2.w += v6.w;
        a3.x += v7.x; a3.y += v7.y; a3.z += v7.z; a3.w += v7.w;
    }
    for (; r < r1; r += GROUPS) {
        float4 v = xv[(size_t)r * D4 + cg];
        a0.x += v.x; a0.y += v.y; a0.z += v.z; a0.w += v.w;
    }
    a0.x += a1.x + a2.x + a3.x;
    a0.y += a1.y + a2.y + a3.y;
    a0.z += a1.z + a2.z + a3.z;
    a0.w += a1.w + a2.w + a3.w;

    // ---- cross-row-group reduction in smem ----
    __shared__ float4 sred[GROUPS][32];
    sred[rg][cg] = a0;
    __syncthreads();

    // write this chunk's partial sum to scratch
    if (tid < 32) {
        float4 s = sred[0][tid];
        #pragma unroll
        for (int g = 1; g < GROUPS; g++) {
            float4 v = sred[g][tid];
            s.x += v.x; s.y += v.y; s.z += v.z; s.w += v.w;
        }
        reinterpret_cast<float4*>(g_part[blockIdx.x])[tid] = s;
    }

    // ---- elect last-arriving chunk of this segment to finalize ----
    __shared__ int is_last;
    __threadfence();
    __syncthreads();
    if (tid == 0) {
        int old = atomicAdd(&g_cnt[b], 1);
        is_last = (old == CHUNKS - 1);
        if (is_last) g_cnt[b] = 0;     // reset for next graph replay
    }
    __syncthreads();

    if (is_last) {
        // all partials visible (threadfence before counter increment)
        float sum = 0.f;
        const int base = b * CHUNKS;
        #pragma unroll
        for (int k = 0; k < CHUNKS; k++)
            sum += g_part[base + k][tid];
        out[(size_t)b * D + tid] = sum / (float)len;
    }
}

extern "C" void kernel_launch(void* const* d_in, const int* in_sizes, int n_in,
                              void* d_out, int out_size)
{
    const float* x    = (const float*)d_in[0];
    const int*   lens = (const int*)d_in[1];
    float*       out  = (float*)d_out;
    const int B = in_sizes[1];

    seg_mean_kernel<<<B * CHUNKS, THREADS>>>(x, lens, out);
}

// round 8
// speedup vs baseline: 1.0934x; 1.0934x over previous
#include <cuda_runtime.h>

#define D 128
#define D4 (D / 4)              // 32 float4 per row
#define THREADS 128
#define CCHUNKS 4               // column chunks per segment (32 cols each)
#define CF4 (D4 / CCHUNKS)      // 8 float4 columns per chunk
#define RGROUPS (THREADS / CF4) // 16 row groups

__global__ __launch_bounds__(THREADS, 8)
void seg_mean_kernel(const float* __restrict__ x,
                     const int* __restrict__ lens,
                     float* __restrict__ out)
{
    const int b   = blockIdx.x >> 2;            // segment
    const int c   = blockIdx.x & (CCHUNKS - 1); // column chunk
    const int tid = threadIdx.x;
    const int lane = tid & 31;
    const int wid  = tid >> 5;

    // ---- segment start = sum(lens[0..b)): strided loads + shfl reduce ----
    __shared__ int ws[4];
    int psum = 0;
    for (int i = tid; i < b; i += THREADS) psum += __ldg(&lens[i]);
    #pragma unroll
    for (int off = 16; off > 0; off >>= 1)
        psum += __shfl_down_sync(0xFFFFFFFFu, psum, off);
    if (lane == 0) ws[wid] = psum;
    __syncthreads();
    const int start = ws[0] + ws[1] + ws[2] + ws[3];
    const int len   = __ldg(&lens[b]);

    // ---- accumulate columns [8c, 8c+8) (float4 units) over all rows ----
    const float4* __restrict__ xv =
        reinterpret_cast<const float4*>(x) + (size_t)start * D4;
    const int cg = c * CF4 + (tid & (CF4 - 1));  // float4 column 0..31
    const int rg = tid >> 3;                     // row group 0..15

    float4 a0 = make_float4(0.f, 0.f, 0.f, 0.f);
    float4 a1 = a0, a2 = a0, a3 = a0;

    int r = rg;
    // 8 independent in-flight LDG.128 per thread, 128 rows/iter per CTA
    for (; r + 7 * RGROUPS < len; r += 8 * RGROUPS) {
        float4 v0 = xv[(size_t)(r + 0 * RGROUPS) * D4 + cg];
        float4 v1 = xv[(size_t)(r + 1 * RGROUPS) * D4 + cg];
        float4 v2 = xv[(size_t)(r + 2 * RGROUPS) * D4 + cg];
        float4 v3 = xv[(size_t)(r + 3 * RGROUPS) * D4 + cg];
        float4 v4 = xv[(size_t)(r + 4 * RGROUPS) * D4 + cg];
        float4 v5 = xv[(size_t)(r + 5 * RGROUPS) * D4 + cg];
        float4 v6 = xv[(size_t)(r + 6 * RGROUPS) * D4 + cg];
        float4 v7 = xv[(size_t)(r + 7 * RGROUPS) * D4 + cg];
        a0.x += v0.x; a0.y += v0.y; a0.z += v0.z; a0.w += v0.w;
        a1.x += v1.x; a1.y += v1.y; a1.z += v1.z; a1.w += v1.w;
        a2.x += v2.x; a2.y += v2.y; a2.z += v2.z; a2.w += v2.w;
        a3.x += v3.x; a3.y += v3.y; a3.z += v3.z; a3.w += v3.w;
        a0.x += v4.x; a0.y += v4.y; a0.z += v4.z; a0.w += v4.w;
        a1.x += v5.x; a1.y += v5.y; a1.z += v5.z; a1.w += v5.w;
        a2.x += v6.x; a2.y += v6.y; a2.z += v6.z; a2.w += v6.w;
        a3.x += v7.x; a3.y += v7.y; a3.z += v7.z; a3.w += v7.w;
    }
    for (; r < len; r += RGROUPS) {
        float4 v = xv[(size_t)r * D4 + cg];
        a0.x += v.x; a0.y += v.y; a0.z += v.z; a0.w += v.w;
    }
    a0.x += a1.x + a2.x + a3.x;
    a0.y += a1.y + a2.y + a3.y;
    a0.z += a1.z + a2.z + a3.z;
    a0.w += a1.w + a2.w + a3.w;

    // ---- reduce 16 row-groups per column in smem ----
    __shared__ float4 sred[RGROUPS][CF4];
    sred[rg][tid & (CF4 - 1)] = a0;
    __syncthreads();

    if (tid < CF4) {
        float4 s = sred[0][tid];
        #pragma unroll
        for (int g = 1; g < RGROUPS; g++) {
            float4 v = sred[g][tid];
            s.x += v.x; s.y += v.y; s.z += v.z; s.w += v.w;
        }
        const float inv = 1.0f / (float)len;
        float4 o = make_float4(s.x * inv, s.y * inv, s.z * inv, s.w * inv);
        reinterpret_cast<float4*>(out)[(size_t)b * D4 + c * CF4 + tid] = o;
    }
}

extern "C" void kernel_launch(void* const* d_in, const int* in_sizes, int n_in,
                              void* d_out, int out_size)
{
    const float* x    = (const float*)d_in[0];
    const int*   lens = (const int*)d_in[1];
    float*       out  = (float*)d_out;
    const int B = in_sizes[1];

    seg_mean_kernel<<<B * CCHUNKS, THREADS>>>(x, lens, out);
}